// round 2
// baseline (speedup 1.0000x reference)
#include <cuda_runtime.h>
#include <math.h>
#include <stdint.h>

#define NN 50000
#define NE 600000
#define FIN 128
#define HID 64
#define HEADS 4
#define C1 (HEADS*HID)   /* 256 */
#define SENTD 768
#define ACT 32

// ---------------- scratch (device globals; no allocation allowed) ----------------
__device__ __align__(16) float g_h1lin[(size_t)NN * C1];   // x@W1, later reused for LN(h1)
__device__ __align__(16) float g_out1 [(size_t)NN * C1];   // layer1 aggregation
__device__ __align__(16) float g_es1[NN * 4];
__device__ __align__(16) float g_ed1[NN * 4];
__device__ __align__(16) float g_denom1[NN * 4];
__device__ __align__(16) float g_rd1[NN * 4];
__device__ __align__(16) float g_ex1[(size_t)NE * 4];
__device__ __align__(16) float g_h2lin[(size_t)NN * HID];
__device__ __align__(16) float g_out2 [(size_t)NN * HID];
__device__ float g_es2[NN], g_ed2[NN], g_denom2[NN], g_rd2[NN];
__device__ float g_ex2[NE];
__device__ float g_sent[HID];

// ---------------- helpers ----------------
__device__ __forceinline__ float warp_sum(float v) {
    #pragma unroll
    for (int o = 16; o; o >>= 1) v += __shfl_xor_sync(0xffffffffu, v, o);
    return v;
}

__device__ __forceinline__ void red_add_v4(float* addr, float x, float y, float z, float w) {
    asm volatile("red.global.add.v4.f32 [%0], {%1,%2,%3,%4};"
                 :: "l"(addr), "f"(x), "f"(y), "f"(z), "f"(w) : "memory");
}

__device__ __forceinline__ float lrelu02(float v) { return v > 0.f ? v : 0.2f * v; }

// ---------------- SGEMM (fp32 SIMT, 128x{128,64} tile, 8x{8,4} per thread) ----------------
template<int BM, int BN, int BK, int TM, int TN>
__global__ void sgemm_kernel(const float* __restrict__ A, const float* __restrict__ B,
                             float* __restrict__ C, int M, int N, int K) {
    constexpr int THREADS = (BM / TM) * (BN / TN);
    __shared__ float As[BK][BM];
    __shared__ float Bs[BK][BN];
    const int tid  = threadIdx.x;
    const int bm   = blockIdx.y * BM;
    const int bn   = blockIdx.x * BN;
    const int tcol = tid % (BN / TN);
    const int trow = tid / (BN / TN);

    float acc[TM][TN];
    #pragma unroll
    for (int i = 0; i < TM; i++)
        #pragma unroll
        for (int j = 0; j < TN; j++) acc[i][j] = 0.f;

    for (int k0 = 0; k0 < K; k0 += BK) {
        // load A tile (transposed into smem)
        for (int i = tid; i < BM * BK / 4; i += THREADS) {
            int r  = i / (BK / 4);
            int kc = (i % (BK / 4)) * 4;
            float4 v = make_float4(0.f, 0.f, 0.f, 0.f);
            if (bm + r < M) v = *(const float4*)&A[(size_t)(bm + r) * K + k0 + kc];
            As[kc + 0][r] = v.x; As[kc + 1][r] = v.y; As[kc + 2][r] = v.z; As[kc + 3][r] = v.w;
        }
        // load B tile
        for (int i = tid; i < BK * BN / 4; i += THREADS) {
            int kr = i / (BN / 4);
            int nc = (i % (BN / 4)) * 4;
            *(float4*)&Bs[kr][nc] = *(const float4*)&B[(size_t)(k0 + kr) * N + bn + nc];
        }
        __syncthreads();
        #pragma unroll
        for (int kk = 0; kk < BK; kk++) {
            float a[TM], b[TN];
            #pragma unroll
            for (int i = 0; i < TM; i += 4)
                *(float4*)&a[i] = *(const float4*)&As[kk][trow * TM + i];
            #pragma unroll
            for (int j = 0; j < TN; j += 4)
                *(float4*)&b[j] = *(const float4*)&Bs[kk][tcol * TN + j];
            #pragma unroll
            for (int i = 0; i < TM; i++)
                #pragma unroll
                for (int j = 0; j < TN; j++) acc[i][j] += a[i] * b[j];
        }
        __syncthreads();
    }
    #pragma unroll
    for (int i = 0; i < TM; i++) {
        int r = bm + trow * TM + i;
        if (r < M) {
            #pragma unroll
            for (int j = 0; j < TN; j += 4) {
                float4 v = make_float4(acc[i][j], acc[i][j+1], acc[i][j+2], acc[i][j+3]);
                *(float4*)&C[(size_t)r * N + bn + tcol * TN + j] = v;
            }
        }
    }
}

// ---------------- zero denominators ----------------
__global__ void zero_kernel() {
    int i = blockIdx.x * blockDim.x + threadIdx.x;
    if (i < NN * 4) g_denom1[i] = 0.f;
    if (i < NN)     g_denom2[i] = 0.f;
}

// ---------------- layer 1 attention scores (per node, per head) ----------------
__global__ void attn1_scores(const float* __restrict__ asrc, const float* __restrict__ adst) {
    int warp = threadIdx.x >> 5, lane = threadIdx.x & 31;
    int node = blockIdx.x * 2 + (warp >> 2);
    int hd   = warp & 3;
    if (node >= NN) return;
    const float* row = g_h1lin + (size_t)node * C1 + hd * HID;
    float v0 = row[lane], v1 = row[lane + 32];
    float s = v0 * asrc[hd * HID + lane] + v1 * asrc[hd * HID + lane + 32];
    float d = v0 * adst[hd * HID + lane] + v1 * adst[hd * HID + lane + 32];
    s = warp_sum(s); d = warp_sum(d);
    if (lane == 0) { g_es1[node * 4 + hd] = s; g_ed1[node * 4 + hd] = d; }
}

// ---------------- layer 1 edge pass A: ex + denom ----------------
__global__ void edge1a(const int* __restrict__ ei) {
    int e = blockIdx.x * blockDim.x + threadIdx.x;
    if (e >= NE) return;
    int s = ei[e], d = ei[NE + e];
    float4 a = *(const float4*)&g_es1[s * 4];
    float4 b = *(const float4*)&g_ed1[d * 4];
    float4 r;
    r.x = expf(lrelu02(a.x + b.x));
    r.y = expf(lrelu02(a.y + b.y));
    r.z = expf(lrelu02(a.z + b.z));
    r.w = expf(lrelu02(a.w + b.w));
    *(float4*)&g_ex1[(size_t)e * 4] = r;
    red_add_v4(&g_denom1[d * 4], r.x, r.y, r.z, r.w);
}

// ---------------- layer 1 node mid: rdenom + self-loop init of out1 ----------------
__global__ void node1mid() {
    int i = blockIdx.x, c = threadIdx.x;
    int hd = c >> 6;
    float s = lrelu02(g_es1[i * 4 + hd] + g_ed1[i * 4 + hd]);
    float exs = expf(s);
    float r = 1.f / (g_denom1[i * 4 + hd] + exs + 1e-16f);
    if (c < 4) {
        float s2 = lrelu02(g_es1[i * 4 + c] + g_ed1[i * 4 + c]);
        float e2 = expf(s2);
        g_rd1[i * 4 + c] = 1.f / (g_denom1[i * 4 + c] + e2 + 1e-16f);
    }
    size_t o = (size_t)i * C1 + c;
    g_out1[o] = g_h1lin[o] * (exs * r);
}

// ---------------- layer 1 edge pass B: scatter h[src]*alpha -> out1[dst] ----------------
__global__ void edge1b(const int* __restrict__ ei) {
    int e = blockIdx.x * 8 + (threadIdx.x >> 5);
    if (e >= NE) return;
    int lane = threadIdx.x & 31;
    int s = ei[e], d = ei[NE + e];
    float4 exv = *(const float4*)&g_ex1[(size_t)e * 4];
    float4 rdv = *(const float4*)&g_rd1[d * 4];
    float al[4] = { exv.x * rdv.x, exv.y * rdv.y, exv.z * rdv.z, exv.w * rdv.w };
    const float4* hs = (const float4*)(g_h1lin + (size_t)s * C1);
    float* od = g_out1 + (size_t)d * C1;
    // first 128 channels
    {
        float4 hv = hs[lane];
        float a = al[lane >> 4];
        red_add_v4(od + lane * 4, hv.x * a, hv.y * a, hv.z * a, hv.w * a);
    }
    // second 128 channels
    {
        float4 hv = hs[32 + lane];
        float a = al[2 + (lane >> 4)];
        red_add_v4(od + 128 + lane * 4, hv.x * a, hv.y * a, hv.z * a, hv.w * a);
    }
}

// ---------------- layer 1 node LN: h1n = LN(elu(out1+b1)) -> g_h1lin (reuse) ----------------
__global__ void node1ln(const float* __restrict__ bias, const float* __restrict__ g,
                        const float* __restrict__ b) {
    __shared__ float sh[18];
    int i = blockIdx.x, c = threadIdx.x, w = c >> 5, l = c & 31;
    float v = g_out1[(size_t)i * C1 + c] + bias[c];
    v = v > 0.f ? v : expm1f(v);
    float s = warp_sum(v), q = warp_sum(v * v);
    if (!l) { sh[w] = s; sh[8 + w] = q; }
    __syncthreads();
    if (c == 0) {
        float S = 0.f, Q = 0.f;
        for (int k = 0; k < 8; k++) { S += sh[k]; Q += sh[8 + k]; }
        float mu = S * (1.f / C1);
        sh[16] = mu;
        sh[17] = rsqrtf(Q * (1.f / C1) - mu * mu + 1e-5f);
    }
    __syncthreads();
    g_h1lin[(size_t)i * C1 + c] = (v - sh[16]) * sh[17] * g[c] + b[c];
}

// ---------------- layer 2 attention scores ----------------
__global__ void attn2_scores(const float* __restrict__ asrc, const float* __restrict__ adst) {
    int warp = threadIdx.x >> 5, lane = threadIdx.x & 31;
    int node = blockIdx.x * 8 + warp;
    if (node >= NN) return;
    const float* row = g_h2lin + (size_t)node * HID;
    float v0 = row[lane], v1 = row[lane + 32];
    float s = v0 * asrc[lane] + v1 * asrc[lane + 32];
    float d = v0 * adst[lane] + v1 * adst[lane + 32];
    s = warp_sum(s); d = warp_sum(d);
    if (lane == 0) { g_es2[node] = s; g_ed2[node] = d; }
}

// ---------------- layer 2 edge pass A ----------------
__global__ void edge2a(const int* __restrict__ ei) {
    int e = blockIdx.x * blockDim.x + threadIdx.x;
    if (e >= NE) return;
    int s = ei[e], d = ei[NE + e];
    float ex = expf(lrelu02(g_es2[s] + g_ed2[d]));
    g_ex2[e] = ex;
    atomicAdd(&g_denom2[d], ex);
}

// ---------------- layer 2 node mid + self alpha ----------------
__global__ void node2mid(float* __restrict__ alpha_out) {
    int i = blockIdx.x * 4 + (threadIdx.x >> 6);
    int c = threadIdx.x & 63;
    if (i >= NN) return;
    float s = lrelu02(g_es2[i] + g_ed2[i]);
    float exs = expf(s);
    float r = 1.f / (g_denom2[i] + exs + 1e-16f);
    g_out2[(size_t)i * HID + c] = g_h2lin[(size_t)i * HID + c] * (exs * r);
    if (c == 0) { g_rd2[i] = r; alpha_out[NE + i] = exs * r; }
}

// ---------------- layer 2 edge pass B: scatter + alpha output ----------------
__global__ void edge2b(const int* __restrict__ ei, float* __restrict__ alpha_out) {
    int e = blockIdx.x * 16 + (threadIdx.x >> 4);
    if (e >= NE) return;
    int sub = threadIdx.x & 15;
    int s = ei[e], d = ei[NE + e];
    float a = g_ex2[e] * g_rd2[d];
    float4 hv = ((const float4*)(g_h2lin + (size_t)s * HID))[sub];
    red_add_v4(g_out2 + (size_t)d * HID + sub * 4, hv.x * a, hv.y * a, hv.z * a, hv.w * a);
    if (sub == 0) alpha_out[e] = a;
}

// ---------------- layer 2 node LN -> d_out h2 region (offset 32!) ----------------
__global__ void node2ln(const float* __restrict__ bias, const float* __restrict__ g,
                        const float* __restrict__ b, float* __restrict__ h2out) {
    __shared__ float sh[6];
    int i = blockIdx.x, c = threadIdx.x, w = c >> 5, l = c & 31;
    float v = g_out2[(size_t)i * HID + c] + bias[c];
    float s = warp_sum(v), q = warp_sum(v * v);
    if (!l) { sh[w] = s; sh[2 + w] = q; }
    __syncthreads();
    if (c == 0) {
        float S = sh[0] + sh[1], Q = sh[2] + sh[3];
        float mu = S * (1.f / HID);
        sh[4] = mu;
        sh[5] = rsqrtf(Q * (1.f / HID) - mu * mu + 1e-5f);
    }
    __syncthreads();
    h2out[(size_t)i * HID + c] = (v - sh[4]) * sh[5] * g[c] + b[c];
}

// ---------------- sentence/step path (tiny, one block of 64) ----------------
__global__ void sent_kernel(const float* __restrict__ semb, const int* __restrict__ stepp,
                            const float* __restrict__ fc0w, const float* __restrict__ fc0b,
                            const float* __restrict__ fc1w, const float* __restrict__ fc1b,
                            const float* __restrict__ fc2w, const float* __restrict__ fc2b,
                            const float* __restrict__ lng, const float* __restrict__ lnb) {
    __shared__ float sh[64];
    __shared__ float st[2];
    int c = threadIdx.x;
    float sval = (float)(stepp[0] + 1) * 0.01f;

    // steps = LN(relu(fc0))
    float t = fmaxf(sval * fc0w[c] + fc0b[c], 0.f);
    sh[c] = t; __syncthreads();
    if (c == 0) {
        float S = 0, Q = 0;
        for (int k = 0; k < 64; k++) { S += sh[k]; Q += sh[k] * sh[k]; }
        float mu = S / 64.f; st[0] = mu; st[1] = rsqrtf(Q / 64.f - mu * mu + 1e-5f);
    }
    __syncthreads();
    float steps_c = (t - st[0]) * st[1] * lng[c] + lnb[c];
    __syncthreads();

    // sent = LN(relu(emb@fc1)) + steps
    float u = fc1b[c];
    for (int k = 0; k < SENTD; k++) u += semb[k] * fc1w[k * 64 + c];
    u = fmaxf(u, 0.f);
    sh[c] = u; __syncthreads();
    if (c == 0) {
        float S = 0, Q = 0;
        for (int k = 0; k < 64; k++) { S += sh[k]; Q += sh[k] * sh[k]; }
        float mu = S / 64.f; st[0] = mu; st[1] = rsqrtf(Q / 64.f - mu * mu + 1e-5f);
    }
    __syncthreads();
    float sc = (u - st[0]) * st[1] * lng[c] + lnb[c] + steps_c;
    __syncthreads();
    sh[c] = sc; __syncthreads();

    // sent = LN(relu(sent@fc2))
    float v = fc2b[c];
    for (int k = 0; k < 64; k++) v += sh[k] * fc2w[k * 64 + c];
    v = fmaxf(v, 0.f);
    __syncthreads();
    sh[c] = v; __syncthreads();
    if (c == 0) {
        float S = 0, Q = 0;
        for (int k = 0; k < 64; k++) { S += sh[k]; Q += sh[k] * sh[k]; }
        float mu = S / 64.f; st[0] = mu; st[1] = rsqrtf(Q / 64.f - mu * mu + 1e-5f);
    }
    __syncthreads();
    g_sent[c] = (v - st[0]) * st[1] * lng[c] + lnb[c];
}

// ---------------- dueling head (tiny, one block of 128) ----------------
__global__ void head_kernel(const float* __restrict__ h2base, const int* __restrict__ activep,
                            const float* __restrict__ fc3w, const float* __restrict__ fc3b,
                            const float* __restrict__ valw, const float* __restrict__ valb,
                            const float* __restrict__ advw, const float* __restrict__ advb,
                            const float* __restrict__ lnfg, const float* __restrict__ lnfb,
                            const float* __restrict__ lnhg, const float* __restrict__ lnhb,
                            float* __restrict__ outlogits) {
    __shared__ float sh[128];
    __shared__ float sh2[64];
    __shared__ float st[3];
    int c = threadIdx.x;
    int act = activep[0];
    // h2 region lives at h2base (already offset to out+32 by host)
    float a = (c < 64) ? h2base[(size_t)act * 64 + c] : g_sent[c - 64];
    sh[c] = a; __syncthreads();
    if (c == 0) {
        float S = 0, Q = 0;
        for (int k = 0; k < 128; k++) { S += sh[k]; Q += sh[k] * sh[k]; }
        float mu = S / 128.f; st[0] = mu; st[1] = rsqrtf(Q / 128.f - mu * mu + 1e-5f);
    }
    __syncthreads();
    float anf = (a - st[0]) * st[1] * lnfg[c] + lnfb[c];
    __syncthreads();
    sh[c] = anf; __syncthreads();

    float t = 0.f;
    if (c < 64) {
        t = fc3b[c];
        for (int k = 0; k < 128; k++) t += sh[k] * fc3w[k * 64 + c];
        t = fmaxf(t, 0.f);
        sh2[c] = t;
    }
    __syncthreads();
    if (c == 0) {
        float S = 0, Q = 0;
        for (int k = 0; k < 64; k++) { S += sh2[k]; Q += sh2[k] * sh2[k]; }
        float mu = S / 64.f; st[0] = mu; st[1] = rsqrtf(Q / 64.f - mu * mu + 1e-5f);
    }
    __syncthreads();
    if (c < 64) sh2[c] = (t - st[0]) * st[1] * lnhg[c] + lnhb[c];
    __syncthreads();
    if (c == 0) {
        float v = valb[0];
        for (int k = 0; k < 64; k++) v += sh2[k] * valw[k];
        st[2] = v;
    }
    __syncthreads();
    float advv = 0.f;
    if (c < 32) {
        advv = advb[c];
        for (int k = 0; k < 64; k++) advv += sh2[k] * advw[k * 32 + c];
        sh[c] = advv;
    }
    __syncthreads();
    if (c == 0) {
        float m = 0;
        for (int k = 0; k < 32; k++) m += sh[k];
        st[0] = m / 32.f;
    }
    __syncthreads();
    if (c < 32) outlogits[c] = tanhf(st[2] + advv - st[0]);
}

// ---------------- launch ----------------
extern "C" void kernel_launch(void* const* d_in, const int* in_sizes, int n_in,
                              void* d_out, int out_size) {
    const float* x      = (const float*)d_in[0];
    const int*   ei     = (const int*)d_in[1];
    const float* semb   = (const float*)d_in[2];
    const int*   active = (const int*)d_in[3];
    const int*   step   = (const int*)d_in[4];
    const float* W1     = (const float*)d_in[5];
    const float* asrc1  = (const float*)d_in[6];
    const float* adst1  = (const float*)d_in[7];
    const float* b1     = (const float*)d_in[8];
    const float* W2     = (const float*)d_in[9];
    const float* asrc2  = (const float*)d_in[10];
    const float* adst2  = (const float*)d_in[11];
    const float* b2     = (const float*)d_in[12];
    const float* fc0w   = (const float*)d_in[13];
    const float* fc0b   = (const float*)d_in[14];
    const float* fc1w   = (const float*)d_in[15];
    const float* fc1b   = (const float*)d_in[16];
    const float* fc2w   = (const float*)d_in[17];
    const float* fc2b   = (const float*)d_in[18];
    const float* fc3w   = (const float*)d_in[19];
    const float* fc3b   = (const float*)d_in[20];
    const float* valw   = (const float*)d_in[21];
    const float* valb   = (const float*)d_in[22];
    const float* advw   = (const float*)d_in[23];
    const float* advb   = (const float*)d_in[24];
    const float* lnhg   = (const float*)d_in[25];
    const float* lnhb   = (const float*)d_in[26];
    const float* lnfg   = (const float*)d_in[27];
    const float* lnfb   = (const float*)d_in[28];
    const float* lnag   = (const float*)d_in[29];
    const float* lnab   = (const float*)d_in[30];
    float* out = (float*)d_out;

    // output layout: logits[32] | h2[NN*64] | alpha[NE+NN]
    float* h2out     = out + 32;
    float* alpha_out = out + 32 + (size_t)NN * HID;

    float* g_h1lin_p; cudaGetSymbolAddress((void**)&g_h1lin_p, g_h1lin);
    float* g_h2lin_p; cudaGetSymbolAddress((void**)&g_h2lin_p, g_h2lin);

    zero_kernel<<<(NN * 4 + 255) / 256, 256>>>();
    sent_kernel<<<1, 64>>>(semb, step, fc0w, fc0b, fc1w, fc1b, fc2w, fc2b, lnhg, lnhb);

    // GEMM1: h1lin = x @ W1   (50000x256, K=128)
    {
        dim3 grid((C1 + 127) / 128, (NN + 127) / 128);
        sgemm_kernel<128, 128, 16, 8, 8><<<grid, 256>>>(x, W1, g_h1lin_p, NN, C1, FIN);
    }
    attn1_scores<<<(NN + 1) / 2, 256>>>(asrc1, adst1);
    edge1a<<<(NE + 255) / 256, 256>>>(ei);
    node1mid<<<NN, 256>>>();
    edge1b<<<(NE + 7) / 8, 256>>>(ei);
    node1ln<<<NN, 256>>>(b1, lnag, lnab);

    // GEMM2: h2lin = h1n @ W2   (50000x64, K=256); h1n lives in g_h1lin
    {
        dim3 grid(1, (NN + 127) / 128);
        sgemm_kernel<128, 64, 16, 8, 4><<<grid, 256>>>(g_h1lin_p, W2, g_h2lin_p, NN, HID, C1);
    }
    attn2_scores<<<(NN + 7) / 8, 256>>>(asrc2, adst2);
    edge2a<<<(NE + 255) / 256, 256>>>(ei);
    node2mid<<<(NN + 3) / 4, 256>>>(alpha_out);
    edge2b<<<(NE + 15) / 16, 256>>>(ei, alpha_out);
    node2ln<<<NN, 64>>>(b2, lnhg, lnhb, h2out);

    head_kernel<<<1, 128>>>(h2out, active, fc3w, fc3b, valw, valb, advw, advb,
                            lnfg, lnfb, lnhg, lnhb, out);
}